// round 15
// baseline (speedup 1.0000x reference)
#include <cuda_runtime.h>
#include <cuda_fp16.h>
#include <cstdint>
#include <math.h>

#define N_NODES 50000
#define N_EDGES 1600000
#define DIM     128
#define RC      5.0f
#define DEPTH   3

#define SCAN_BLK 1024
#define N_CHUNKS ((N_NODES + SCAN_BLK - 1) / SCAN_BLK)   // 49

// ---------------- persistent device scratch (no allocation APIs) -------------
__device__ int    g_counts[N_NODES];
__device__ int    g_rowloc[N_NODES + 1];        // chunk-local inclusive scan
__device__ int    g_rowptr[N_NODES + 1];        // finalized CSR row pointers
__device__ int    g_bsum[N_CHUNKS];             // per-chunk totals
__device__ int    g_slot[N_EDGES];              // per-edge slot within its dst list
__device__ int2   g_csr[N_EDGES];               // (src, f as duplicated half2)
__device__ __half g_curh[N_NODES * DIM];        // fp16 current features (gather source)
__device__ __half g_xh[N_NODES * DIM];          // fp16 x = segment_sum + v (GEMM input)
__device__ __half g_Ah[DIM * DIM];              // fp16 copy of A_w (converted once)

// ---------------------------------------------------------------------------
// histogram + slot assignment + fp16 copies of v and A (one pass, 1.6M threads)
__global__ void k_hist(const int* __restrict__ dst, const float* __restrict__ v,
                       const float* __restrict__ A)
{
    int e = blockIdx.x * blockDim.x + threadIdx.x;
    if (e >= N_EDGES) return;
    g_slot[e] = atomicAdd(&g_counts[dst[e]], 1);
    // v -> fp16 (e indexes float4 quads; N_NODES*32 quads == N_EDGES threads)
    float4 f = reinterpret_cast<const float4*>(v)[e];
    __half2 h0 = __floats2half2_rn(f.x, f.y);
    __half2 h1 = __floats2half2_rn(f.z, f.w);
    uint2 raw;
    raw.x = *reinterpret_cast<unsigned*>(&h0);
    raw.y = *reinterpret_cast<unsigned*>(&h1);
    reinterpret_cast<uint2*>(g_curh)[e] = raw;
    // A_w -> fp16 once (16384 elements)
    if (e < DIM * DIM) g_Ah[e] = __float2half_rn(A[e]);
}

// per-chunk inclusive scan (chunk-local only; no cross-chunk dependency)
__global__ void __launch_bounds__(SCAN_BLK)
k_scan1()
{
    __shared__ int s[SCAN_BLK];
    int t = threadIdx.x;
    int i = blockIdx.x * SCAN_BLK + t;
    s[t] = (i < N_NODES) ? g_counts[i] : 0;
    __syncthreads();
    for (int off = 1; off < SCAN_BLK; off <<= 1) {
        int add = (t >= off) ? s[t - off] : 0;
        __syncthreads();
        s[t] += add;
        __syncthreads();
    }
    if (i < N_NODES) g_rowloc[i + 1] = s[t];
    if (t == SCAN_BLK - 1) g_bsum[blockIdx.x] = s[t];
    if (i == 0) { g_rowloc[0] = 0; g_rowptr[0] = 0; }
}

// CSR fill + rowptr finalize. Each block rebuilds the 49-entry chunk-offset
// LUT in shared memory (cheap) -- no grid sync anywhere.
__global__ void __launch_bounds__(256)
k_fill(const int* __restrict__ src, const int* __restrict__ dst,
       const float* __restrict__ e_in,
       const float* __restrict__ rs, const float* __restrict__ sigma)
{
    __shared__ int lut[N_CHUNKS];                 // exclusive prefix of chunk sums
    if (threadIdx.x == 0) {
        int run = 0;
        for (int c = 0; c < N_CHUNKS; c++) { lut[c] = run; run += g_bsum[c]; }
    }
    __syncthreads();

    int stride = gridDim.x * blockDim.x;
    int t0 = blockIdx.x * blockDim.x + threadIdx.x;

    // finalize rowptr for the aggregate kernel
    for (int i = t0; i < N_NODES; i += stride)
        g_rowptr[i + 1] = g_rowloc[i + 1] + lut[i >> 10];

    // scatter edges into CSR order; envelope f stored as duplicated half2
    float rsv = rs[0], sg = sigma[0];
    for (int e = t0; e < N_EDGES; e += stride) {
        int n = dst[e];
        int base = (n == 0) ? 0 : (g_rowloc[n] + lut[(n - 1) >> 10]);
        int p = base + g_slot[e];
        float r   = e_in[e];
        float d   = r - rsv;
        float gau = expf(-(d * d) / (sg * sg));
        float cut = (r < RC) ? 0.5f * cosf(0.62831853071795864769f * r) : 0.0f; // pi/RC
        __half2 fh = __float2half2_rn(gau * cut);
        g_csr[p] = make_int2(src[e], (int)*reinterpret_cast<unsigned*>(&fh));
    }
}

// one warp per node: xh[n] = fp16( v[n] + sum_{edges->n} f * curh[src] )
// Full warp per edge (uint2/lane). HFMA2 accumulation, fp32 flush every
// 4 edges; f pre-packed half2 in g_csr; pure 32-bit address math.
__global__ void __launch_bounds__(256)
k_aggregate(const float* __restrict__ v)
{
    __shared__ int2 s_meta[8][32];
    int gtid = blockIdx.x * blockDim.x + threadIdx.x;
    int node = gtid >> 5;
    int lane = gtid & 31;
    int w    = threadIdx.x >> 5;
    if (node >= N_NODES) return;

    int p0 = __ldg(&g_rowptr[node]);
    int p1 = __ldg(&g_rowptr[node + 1]);

    const uint2* in = reinterpret_cast<const uint2*>(g_curh);  // 4 halfs per lane
    float4 accf = make_float4(0.f, 0.f, 0.f, 0.f);
    const __half2 hz = __float2half2_rn(0.f);

    for (int base = p0; base < p1; base += 32) {
        int idx = base + lane;
        if (idx < p1) s_meta[w][lane] = __ldg(&g_csr[idx]);
        __syncwarp();
        int cnt = min(32, p1 - base);
        for (int j0 = 0; j0 < cnt; j0 += 4) {
            __half2 h0 = hz, h1 = hz;
            int je = min(j0 + 4, cnt);
#pragma unroll 4
            for (int j = j0; j < je; j++) {
                int2 m = s_meta[w][j];
                __half2 fh = *reinterpret_cast<__half2*>(&m.y);
                uint2 r = __ldg(&in[(unsigned)m.x * 32u + (unsigned)lane]);
                h0 = __hfma2(fh, *reinterpret_cast<__half2*>(&r.x), h0);
                h1 = __hfma2(fh, *reinterpret_cast<__half2*>(&r.y), h1);
            }
            float2 f0 = __half22float2(h0);
            float2 f1 = __half22float2(h1);
            accf.x += f0.x; accf.y += f0.y; accf.z += f1.x; accf.w += f1.y;
        }
        __syncwarp();
    }

    float4 vv = *reinterpret_cast<const float4*>(v + (size_t)node * DIM + lane * 4);
    accf.x += vv.x; accf.y += vv.y; accf.z += vv.z; accf.w += vv.w;
    __half2 o0 = __floats2half2_rn(accf.x, accf.y);
    __half2 o1 = __floats2half2_rn(accf.z, accf.w);
    uint2 raw;
    raw.x = *reinterpret_cast<unsigned*>(&o0);
    raw.y = *reinterpret_cast<unsigned*>(&o1);
    reinterpret_cast<uint2*>(g_xh)[(unsigned)node * 32u + (unsigned)lane] = raw;
}

// out = relu(x @ A^T + b) on tensor cores: mma.sync m16n8k16 f16 -> f32.
// Block 256 thr = 8 warps; tile 128 rows x 128 cols; warp = 16 rows x 128 cols.
// A comes pre-converted from g_Ah (fp16): no per-block conversion, half traffic.
#define LIN_ROWS 128
#define PADK     136   // smem stride in halfs: word stride 68 -> conflict-free frags
__global__ void __launch_bounds__(256, 2)
k_linear(const float* __restrict__ b, float* __restrict__ dout, int last)
{
    extern __shared__ __half smem[];
    __half* As = smem;                       // [c][k] stride PADK  (B operand)
    __half* xs = smem + DIM * PADK;          // [m][k] stride PADK  (A operand)

    int tid  = threadIdx.x;
    int wid  = tid >> 5;
    int lane = tid & 31;
    int g    = lane >> 2;                    // 0..7
    int tg   = lane & 3;                     // 0..3
    int m0   = wid * 16;                     // warp's 16-row band

    int row0 = blockIdx.x * LIN_ROWS;

    // As: copy fp16 A (16384 halfs = 2048 uint4), layout [c][k] native
    {
        const uint4* A4 = reinterpret_cast<const uint4*>(g_Ah);
        for (int i = tid; i < DIM * DIM / 8; i += 256) {    // uint4 units (8 halfs)
            int c = i >> 4, kk = i & 15;
            uint4 val = A4[i];
            *reinterpret_cast<uint4*>(As + c * PADK + kk * 8) = val;
        }
        const uint4* X4 = reinterpret_cast<const uint4*>(g_xh);
        uint4 zero4 = make_uint4(0u, 0u, 0u, 0u);
        for (int i = tid; i < LIN_ROWS * 16; i += 256) {    // 16 uint4 per row
            int r = i >> 4, kk = i & 15;
            uint4 val = (row0 + r < N_NODES) ? X4[(size_t)(row0 + r) * 16 + kk] : zero4;
            *reinterpret_cast<uint4*>(xs + r * PADK + kk * 8) = val;
        }
    }
    __syncthreads();

    float d[16][4];
#pragma unroll
    for (int nt = 0; nt < 16; nt++)
#pragma unroll
        for (int j = 0; j < 4; j++) d[nt][j] = 0.f;

    const unsigned* xsu = reinterpret_cast<const unsigned*>(xs);
    const unsigned* asu = reinterpret_cast<const unsigned*>(As);

#pragma unroll
    for (int kt = 0; kt < 8; kt++) {
        int k0 = kt * 16;
        unsigned a0 = xsu[(m0 + g)     * 68 + (k0 >> 1) + tg];
        unsigned a1 = xsu[(m0 + g + 8) * 68 + (k0 >> 1) + tg];
        unsigned a2 = xsu[(m0 + g)     * 68 + (k0 >> 1) + tg + 4];
        unsigned a3 = xsu[(m0 + g + 8) * 68 + (k0 >> 1) + tg + 4];
#pragma unroll
        for (int nt = 0; nt < 16; nt++) {
            int n = nt * 8 + g;
            unsigned b0 = asu[n * 68 + (k0 >> 1) + tg];
            unsigned b1 = asu[n * 68 + (k0 >> 1) + tg + 4];
            asm volatile(
                "mma.sync.aligned.m16n8k16.row.col.f32.f16.f16.f32 "
                "{%0,%1,%2,%3}, {%4,%5,%6,%7}, {%8,%9}, {%0,%1,%2,%3};"
                : "+f"(d[nt][0]), "+f"(d[nt][1]), "+f"(d[nt][2]), "+f"(d[nt][3])
                : "r"(a0), "r"(a1), "r"(a2), "r"(a3), "r"(b0), "r"(b1));
        }
    }

    // epilogue: bias + relu; thread owns cols {nt*8+2tg,+1}, rows {m0+g, m0+g+8}
    int r0 = row0 + m0 + g;
    int r1 = r0 + 8;
#pragma unroll
    for (int nt = 0; nt < 16; nt++) {
        int col = nt * 8 + tg * 2;
        float2 bb = *reinterpret_cast<const float2*>(b + col);
        float o0 = fmaxf(d[nt][0] + bb.x, 0.f);
        float o1 = fmaxf(d[nt][1] + bb.y, 0.f);
        float o2 = fmaxf(d[nt][2] + bb.x, 0.f);
        float o3 = fmaxf(d[nt][3] + bb.y, 0.f);
        if (last) {
            if (r0 < N_NODES)
                *reinterpret_cast<float2*>(dout + (size_t)r0 * DIM + col) = make_float2(o0, o1);
            if (r1 < N_NODES)
                *reinterpret_cast<float2*>(dout + (size_t)r1 * DIM + col) = make_float2(o2, o3);
        } else {
            unsigned* ch = reinterpret_cast<unsigned*>(g_curh);
            if (r0 < N_NODES) {
                __half2 h = __floats2half2_rn(o0, o1);
                ch[(size_t)r0 * 64 + (col >> 1)] = *reinterpret_cast<unsigned*>(&h);
            }
            if (r1 < N_NODES) {
                __half2 h = __floats2half2_rn(o2, o3);
                ch[(size_t)r1 * 64 + (col >> 1)] = *reinterpret_cast<unsigned*>(&h);
            }
        }
    }
}

// ---------------------------------------------------------------------------
extern "C" void kernel_launch(void* const* d_in, const int* in_sizes, int n_in,
                              void* d_out, int out_size)
{
    const float* v     = (const float*)d_in[0];
    const float* e     = (const float*)d_in[1];
    const int*   src   = (const int*)d_in[2];
    const int*   dst   = (const int*)d_in[3];
    const float* A_w   = (const float*)d_in[4];
    const float* A_b   = (const float*)d_in[5];
    const float* rs    = (const float*)d_in[6];
    const float* sigma = (const float*)d_in[7];
    float* out = (float*)d_out;

    (void)in_sizes; (void)n_in; (void)out_size;

    const int SMEM_LIN = (DIM + LIN_ROWS) * PADK * (int)sizeof(__half); // ~68KB
    (void)cudaFuncSetAttribute(k_linear, cudaFuncAttributeMaxDynamicSharedMemorySize, SMEM_LIN);

    // zero the histogram with a memset node (graph-capturable, not an alloc)
    void* counts_ptr = nullptr;
    (void)cudaGetSymbolAddress(&counts_ptr, g_counts);
    (void)cudaMemsetAsync(counts_ptr, 0, N_NODES * sizeof(int));

    int gE = (N_EDGES + 255) / 256;

    k_hist <<<gE, 256>>>(dst, v, A_w);
    k_scan1<<<N_CHUNKS, SCAN_BLK>>>();
    k_fill <<<2048, 256>>>(src, dst, e, rs, sigma);

    int aggBlocks = (N_NODES * 32 + 255) / 256;           // warp per node
    int linBlocks = (N_NODES + LIN_ROWS - 1) / LIN_ROWS;  // 391

    for (int d = 0; d < DEPTH; d++) {
        k_aggregate<<<aggBlocks, 256>>>(v);
        k_linear<<<linBlocks, 256, SMEM_LIN>>>(A_b, out, d == DEPTH - 1 ? 1 : 0);
    }
}

// round 16
// speedup vs baseline: 1.1758x; 1.1758x over previous
#include <cuda_runtime.h>
#include <cuda_fp16.h>
#include <cstdint>
#include <math.h>

#define N_NODES 50000
#define N_EDGES 1600000
#define DIM     128
#define RC      5.0f
#define DEPTH   3

#define SCAN_BLK 1024
#define N_CHUNKS ((N_NODES + SCAN_BLK - 1) / SCAN_BLK)   // 49

// ---------------- persistent device scratch (no allocation APIs) -------------
__device__ int    g_counts[N_NODES];
__device__ int    g_rowloc[N_NODES + 1];        // chunk-local inclusive scan
__device__ int    g_rowptr[N_NODES + 1];        // finalized CSR row pointers
__device__ int    g_bsum[N_CHUNKS];             // per-chunk totals
__device__ int    g_slot[N_EDGES];              // per-edge slot within its dst list
__device__ int2   g_csr[N_EDGES];               // (src, f as duplicated half2)
__device__ __half g_curh[N_NODES * DIM];        // fp16 current features (gather source)
__device__ __half g_xh[N_NODES * DIM];          // fp16 x = segment_sum + v (GEMM input)
__device__ __half g_Ah[DIM * DIM];              // fp16 copy of A_w (converted once)

// ---------------------------------------------------------------------------
// histogram + slot assignment + fp16 copies of v and A (one pass, 1.6M threads)
__global__ void k_hist(const int* __restrict__ dst, const float* __restrict__ v,
                       const float* __restrict__ A)
{
    int e = blockIdx.x * blockDim.x + threadIdx.x;
    if (e >= N_EDGES) return;
    g_slot[e] = atomicAdd(&g_counts[dst[e]], 1);
    // v -> fp16 (e indexes float4 quads; N_NODES*32 quads == N_EDGES threads)
    float4 f = reinterpret_cast<const float4*>(v)[e];
    __half2 h0 = __floats2half2_rn(f.x, f.y);
    __half2 h1 = __floats2half2_rn(f.z, f.w);
    uint2 raw;
    raw.x = *reinterpret_cast<unsigned*>(&h0);
    raw.y = *reinterpret_cast<unsigned*>(&h1);
    reinterpret_cast<uint2*>(g_curh)[e] = raw;
    // A_w -> fp16 once (16384 elements)
    if (e < DIM * DIM) g_Ah[e] = __float2half_rn(A[e]);
}

// per-chunk inclusive scan (chunk-local only; no cross-chunk dependency)
__global__ void __launch_bounds__(SCAN_BLK)
k_scan1()
{
    __shared__ int s[SCAN_BLK];
    int t = threadIdx.x;
    int i = blockIdx.x * SCAN_BLK + t;
    s[t] = (i < N_NODES) ? g_counts[i] : 0;
    __syncthreads();
    for (int off = 1; off < SCAN_BLK; off <<= 1) {
        int add = (t >= off) ? s[t - off] : 0;
        __syncthreads();
        s[t] += add;
        __syncthreads();
    }
    if (i < N_NODES) g_rowloc[i + 1] = s[t];
    if (t == SCAN_BLK - 1) g_bsum[blockIdx.x] = s[t];
    if (i == 0) { g_rowloc[0] = 0; g_rowptr[0] = 0; }
}

// CSR fill + rowptr finalize. Each block rebuilds the 49-entry chunk-offset
// LUT in shared memory (cheap) -- no grid sync anywhere.
__global__ void __launch_bounds__(256)
k_fill(const int* __restrict__ src, const int* __restrict__ dst,
       const float* __restrict__ e_in,
       const float* __restrict__ rs, const float* __restrict__ sigma)
{
    __shared__ int lut[N_CHUNKS];                 // exclusive prefix of chunk sums
    if (threadIdx.x == 0) {
        int run = 0;
        for (int c = 0; c < N_CHUNKS; c++) { lut[c] = run; run += g_bsum[c]; }
    }
    __syncthreads();

    int stride = gridDim.x * blockDim.x;
    int t0 = blockIdx.x * blockDim.x + threadIdx.x;

    // finalize rowptr for the aggregate kernel
    for (int i = t0; i < N_NODES; i += stride)
        g_rowptr[i + 1] = g_rowloc[i + 1] + lut[i >> 10];

    // scatter edges into CSR order; envelope f stored as duplicated half2
    float rsv = rs[0], sg = sigma[0];
    for (int e = t0; e < N_EDGES; e += stride) {
        int n = dst[e];
        int base = (n == 0) ? 0 : (g_rowloc[n] + lut[(n - 1) >> 10]);
        int p = base + g_slot[e];
        float r   = e_in[e];
        float d   = r - rsv;
        float gau = expf(-(d * d) / (sg * sg));
        float cut = (r < RC) ? 0.5f * cosf(0.62831853071795864769f * r) : 0.0f; // pi/RC
        __half2 fh = __float2half2_rn(gau * cut);
        g_csr[p] = make_int2(src[e], (int)*reinterpret_cast<unsigned*>(&fh));
    }
}

// one warp per node: xh[n] = fp16( v[n] + sum_{edges->n} f * curh[src] )
// Half-warp per edge (16 lanes x uint4 = 256B row), 2 edges per warp-iter.
// fp16 HFMA2 accumulation, flushed to fp32 every 8 edges; cross-half
// shfl_xor(16) reduction at the end.  [best-measured variant: R13, 41.1us]
__global__ void __launch_bounds__(256)
k_aggregate(const float* __restrict__ v)
{
    __shared__ int2 s_meta[8][32];
    int gtid = blockIdx.x * blockDim.x + threadIdx.x;
    int node = gtid >> 5;
    int lane = gtid & 31;
    int w    = threadIdx.x >> 5;
    if (node >= N_NODES) return;

    int half_id = lane >> 4;      // which edge of the pair
    int sub     = lane & 15;      // 8-dim group within row (uint4 index)

    int p0 = __ldg(&g_rowptr[node]);
    int p1 = __ldg(&g_rowptr[node + 1]);

    const uint4* in = reinterpret_cast<const uint4*>(g_curh);  // 16 uint4 per row

    float accf[8];
#pragma unroll
    for (int i = 0; i < 8; i++) accf[i] = 0.f;

    const __half2 hzero = __float2half2_rn(0.f);

    for (int base = p0; base < p1; base += 32) {
        int idx = base + lane;
        if (idx < p1) s_meta[w][lane] = __ldg(&g_csr[idx]);
        __syncwarp();
        int cnt = min(32, p1 - base);
        for (int j2 = 0; j2 < cnt; j2 += 8) {
            __half2 h0 = hzero, h1 = hzero, h2 = hzero, h3 = hzero;
#pragma unroll
            for (int u = 0; u < 4; u++) {
                int j = j2 + u * 2 + half_id;
                bool act = j < cnt;
                int2 m = s_meta[w][act ? j : 0];
                unsigned fb = act ? (unsigned)m.y : 0u;
                __half2 fh = *reinterpret_cast<__half2*>(&fb);
                uint4 r = __ldg(&in[(size_t)m.x * 16 + sub]);
                h0 = __hfma2(fh, *reinterpret_cast<__half2*>(&r.x), h0);
                h1 = __hfma2(fh, *reinterpret_cast<__half2*>(&r.y), h1);
                h2 = __hfma2(fh, *reinterpret_cast<__half2*>(&r.z), h2);
                h3 = __hfma2(fh, *reinterpret_cast<__half2*>(&r.w), h3);
            }
            float2 f0 = __half22float2(h0);
            float2 f1 = __half22float2(h1);
            float2 f2 = __half22float2(h2);
            float2 f3 = __half22float2(h3);
            accf[0] += f0.x; accf[1] += f0.y;
            accf[2] += f1.x; accf[3] += f1.y;
            accf[4] += f2.x; accf[5] += f2.y;
            accf[6] += f3.x; accf[7] += f3.y;
        }
        __syncwarp();
    }

    // merge the two half-warp partial sums (same dims, different edges)
#pragma unroll
    for (int i = 0; i < 8; i++)
        accf[i] += __shfl_xor_sync(0xffffffffu, accf[i], 16);

    if (half_id == 0) {
        const float4* vr = reinterpret_cast<const float4*>(v + (size_t)node * DIM + sub * 8);
        float4 v0 = vr[0];
        float4 v1 = vr[1];
        accf[0] += v0.x; accf[1] += v0.y; accf[2] += v0.z; accf[3] += v0.w;
        accf[4] += v1.x; accf[5] += v1.y; accf[6] += v1.z; accf[7] += v1.w;
        __half2 o0 = __floats2half2_rn(accf[0], accf[1]);
        __half2 o1 = __floats2half2_rn(accf[2], accf[3]);
        __half2 o2 = __floats2half2_rn(accf[4], accf[5]);
        __half2 o3 = __floats2half2_rn(accf[6], accf[7]);
        uint4 raw;
        raw.x = *reinterpret_cast<unsigned*>(&o0);
        raw.y = *reinterpret_cast<unsigned*>(&o1);
        raw.z = *reinterpret_cast<unsigned*>(&o2);
        raw.w = *reinterpret_cast<unsigned*>(&o3);
        reinterpret_cast<uint4*>(g_xh)[(size_t)node * 16 + sub] = raw;
    }
}

// out = relu(x @ A^T + b) on tensor cores: mma.sync m16n8k16 f16 -> f32.
// Block 256 thr = 8 warps; tile 128 rows x 128 cols; warp = 16 rows x 128 cols.
// A comes pre-converted from g_Ah (fp16): no per-block conversion, half traffic.
#define LIN_ROWS 128
#define PADK     136   // smem stride in halfs: word stride 68 -> conflict-free frags
__global__ void __launch_bounds__(256, 2)
k_linear(const float* __restrict__ b, float* __restrict__ dout, int last)
{
    extern __shared__ __half smem[];
    __half* As = smem;                       // [c][k] stride PADK  (B operand)
    __half* xs = smem + DIM * PADK;          // [m][k] stride PADK  (A operand)

    int tid  = threadIdx.x;
    int wid  = tid >> 5;
    int lane = tid & 31;
    int g    = lane >> 2;                    // 0..7
    int tg   = lane & 3;                     // 0..3
    int m0   = wid * 16;                     // warp's 16-row band

    int row0 = blockIdx.x * LIN_ROWS;

    // As: copy fp16 A (16384 halfs = 2048 uint4), layout [c][k] native
    {
        const uint4* A4 = reinterpret_cast<const uint4*>(g_Ah);
        for (int i = tid; i < DIM * DIM / 8; i += 256) {    // uint4 units (8 halfs)
            int c = i >> 4, kk = i & 15;
            uint4 val = A4[i];
            *reinterpret_cast<uint4*>(As + c * PADK + kk * 8) = val;
        }
        const uint4* X4 = reinterpret_cast<const uint4*>(g_xh);
        uint4 zero4 = make_uint4(0u, 0u, 0u, 0u);
        for (int i = tid; i < LIN_ROWS * 16; i += 256) {    // 16 uint4 per row
            int r = i >> 4, kk = i & 15;
            uint4 val = (row0 + r < N_NODES) ? X4[(size_t)(row0 + r) * 16 + kk] : zero4;
            *reinterpret_cast<uint4*>(xs + r * PADK + kk * 8) = val;
        }
    }
    __syncthreads();

    float d[16][4];
#pragma unroll
    for (int nt = 0; nt < 16; nt++)
#pragma unroll
        for (int j = 0; j < 4; j++) d[nt][j] = 0.f;

    const unsigned* xsu = reinterpret_cast<const unsigned*>(xs);
    const unsigned* asu = reinterpret_cast<const unsigned*>(As);

#pragma unroll
    for (int kt = 0; kt < 8; kt++) {
        int k0 = kt * 16;
        unsigned a0 = xsu[(m0 + g)     * 68 + (k0 >> 1) + tg];
        unsigned a1 = xsu[(m0 + g + 8) * 68 + (k0 >> 1) + tg];
        unsigned a2 = xsu[(m0 + g)     * 68 + (k0 >> 1) + tg + 4];
        unsigned a3 = xsu[(m0 + g + 8) * 68 + (k0 >> 1) + tg + 4];
#pragma unroll
        for (int nt = 0; nt < 16; nt++) {
            int n = nt * 8 + g;
            unsigned b0 = asu[n * 68 + (k0 >> 1) + tg];
            unsigned b1 = asu[n * 68 + (k0 >> 1) + tg + 4];
            asm volatile(
                "mma.sync.aligned.m16n8k16.row.col.f32.f16.f16.f32 "
                "{%0,%1,%2,%3}, {%4,%5,%6,%7}, {%8,%9}, {%0,%1,%2,%3};"
                : "+f"(d[nt][0]), "+f"(d[nt][1]), "+f"(d[nt][2]), "+f"(d[nt][3])
                : "r"(a0), "r"(a1), "r"(a2), "r"(a3), "r"(b0), "r"(b1));
        }
    }

    // epilogue: bias + relu; thread owns cols {nt*8+2tg,+1}, rows {m0+g, m0+g+8}
    int r0 = row0 + m0 + g;
    int r1 = r0 + 8;
#pragma unroll
    for (int nt = 0; nt < 16; nt++) {
        int col = nt * 8 + tg * 2;
        float2 bb = *reinterpret_cast<const float2*>(b + col);
        float o0 = fmaxf(d[nt][0] + bb.x, 0.f);
        float o1 = fmaxf(d[nt][1] + bb.y, 0.f);
        float o2 = fmaxf(d[nt][2] + bb.x, 0.f);
        float o3 = fmaxf(d[nt][3] + bb.y, 0.f);
        if (last) {
            if (r0 < N_NODES)
                *reinterpret_cast<float2*>(dout + (size_t)r0 * DIM + col) = make_float2(o0, o1);
            if (r1 < N_NODES)
                *reinterpret_cast<float2*>(dout + (size_t)r1 * DIM + col) = make_float2(o2, o3);
        } else {
            unsigned* ch = reinterpret_cast<unsigned*>(g_curh);
            if (r0 < N_NODES) {
                __half2 h = __floats2half2_rn(o0, o1);
                ch[(size_t)r0 * 64 + (col >> 1)] = *reinterpret_cast<unsigned*>(&h);
            }
            if (r1 < N_NODES) {
                __half2 h = __floats2half2_rn(o2, o3);
                ch[(size_t)r1 * 64 + (col >> 1)] = *reinterpret_cast<unsigned*>(&h);
            }
        }
    }
}

// ---------------------------------------------------------------------------
extern "C" void kernel_launch(void* const* d_in, const int* in_sizes, int n_in,
                              void* d_out, int out_size)
{
    const float* v     = (const float*)d_in[0];
    const float* e     = (const float*)d_in[1];
    const int*   src   = (const int*)d_in[2];
    const int*   dst   = (const int*)d_in[3];
    const float* A_w   = (const float*)d_in[4];
    const float* A_b   = (const float*)d_in[5];
    const float* rs    = (const float*)d_in[6];
    const float* sigma = (const float*)d_in[7];
    float* out = (float*)d_out;

    (void)in_sizes; (void)n_in; (void)out_size;

    const int SMEM_LIN = (DIM + LIN_ROWS) * PADK * (int)sizeof(__half); // ~68KB
    (void)cudaFuncSetAttribute(k_linear, cudaFuncAttributeMaxDynamicSharedMemorySize, SMEM_LIN);

    // zero the histogram with a memset node (graph-capturable, not an alloc)
    void* counts_ptr = nullptr;
    (void)cudaGetSymbolAddress(&counts_ptr, g_counts);
    (void)cudaMemsetAsync(counts_ptr, 0, N_NODES * sizeof(int));

    int gE = (N_EDGES + 255) / 256;

    k_hist <<<gE, 256>>>(dst, v, A_w);
    k_scan1<<<N_CHUNKS, SCAN_BLK>>>();
    k_fill <<<2048, 256>>>(src, dst, e, rs, sigma);

    int aggBlocks = (N_NODES * 32 + 255) / 256;           // warp per node
    int linBlocks = (N_NODES + LIN_ROWS - 1) / LIN_ROWS;  // 391

    for (int d = 0; d < DEPTH; d++) {
        k_aggregate<<<aggBlocks, 256>>>(v);
        k_linear<<<linBlocks, 256, SMEM_LIN>>>(A_b, out, d == DEPTH - 1 ? 1 : 0);
    }
}